// round 3
// baseline (speedup 1.0000x reference)
#include <cuda_runtime.h>
#include <cstdint>

#define BI 32
#define HH 512
#define WW 512
#define HW (HH*WW)
#define BAND 64

// Bitmask scratch: bit c of word i of row r = pixel (r, i*64+c)
__device__ unsigned long long g_strong[BI][HH][8];
__device__ unsigned long long g_weak[BI][HH][8];

// u8 = floor(clip((x+1)*0.5*256, 0, 255)); (v+1)*0.5*256 == (v+1)*128 exactly
__device__ __forceinline__ float pix_u8(float v){
    float t = __fmul_rn(__fadd_rn(v, 1.0f), 128.0f);
    t = fminf(fmaxf(t, 0.0f), 255.0f);
    return floorf(t);
}

// gray = round(0.299r + 0.587g + 0.114b), no FMA contraction, left-assoc, round-half-even
__device__ __forceinline__ float grayv(float r, float g, float b){
    return rintf(__fadd_rn(__fadd_rn(__fmul_rn(0.299f, r), __fmul_rn(0.587f, g)),
                           __fmul_rn(0.114f, b)));
}

// Exact fp32 integer direction binning (gx,gy integers, |.| <= 1020; all products < 2^24)
//   b0: ay < (sqrt2-1)*ax  <=>  (ay+ax)^2 < 2*ax^2
//   b2: ay > (sqrt2+1)*ax  <=>  (ay>ax) && (ay-ax)^2 > 2*ax^2
__device__ __forceinline__ int binOf(float gx, float gy){
    float ax = fabsf(gx), ay = fabsf(gy);
    float sum = __fadd_rn(ax, ay);
    float a2  = __fmul_rn(2.0f, __fmul_rn(ax, ax));
    if (__fmul_rn(sum, sum) < a2) return 0;
    float dif = __fadd_rn(ay, -ax);
    if (dif > 0.0f && __fmul_rn(dif, dif) > a2) return 2;
    return (__fmul_rn(gx, gy) > 0.0f) ? 1 : 3;
}

// spread bits of 32-bit x to even bit positions of a u64
__device__ __forceinline__ unsigned long long spread1(unsigned x){
    unsigned long long s = x;
    s = (s | (s << 16)) & 0x0000FFFF0000FFFFull;
    s = (s | (s << 8))  & 0x00FF00FF00FF00FFull;
    s = (s | (s << 4))  & 0x0F0F0F0F0F0F0F0Full;
    s = (s | (s << 2))  & 0x3333333333333333ull;
    s = (s | (s << 1))  & 0x5555555555555555ull;
    return s;
}

// Rolling warp pipeline: warp = 64-column strip (lane -> cols c0+2k, c0+2k+1),
// marches down a 64-row band. No shared memory, no barriers.
__global__ __launch_bounds__(256) void canny_stage1(const float* __restrict__ x){
    int b    = blockIdx.y;            // image
    int r0   = blockIdx.x * BAND;     // first emitted row
    int warp = threadIdx.x >> 5;      // strip 0..7
    int lane = threadIdx.x & 31;
    int c0   = warp * 64;
    int cE   = c0 + 2*lane;

    const float* xr = x + (size_t)b*3*HW;
    const float* xg = xr + HW;
    const float* xb = xg + HW;

    bool eL = (lane == 0);
    bool eR = (lane == 31);
    bool edge = eL || eR;
    int colA = eL ? max(c0-1, 0) : min(c0+64, WW-1);   // nearest halo col (replicate clamp)
    int colB = eL ? max(c0-2, 0) : min(c0+65, WW-1);   // 2nd halo col
    bool Aout = (eL && c0 == 0) || (eR && c0+64 >= WW); // mag halo col outside image -> 0

    // gray rows r-1, r, r+1 rolling (E=even col, O=odd col; A/B = edge halo cols)
    float gE0,gO0,gE1,gO1,gE2,gO2;
    float gA0=0,gB0=0,gA1=0,gB1=0,gA2=0,gB2=0;

    {
        int rm2 = max(r0-2, 0), rm1 = max(r0-1, 0);
        int o2 = rm2*WW + cE, o1 = rm1*WW + cE;
        float2 r2a = *(const float2*)(xr+o2), g2a = *(const float2*)(xg+o2), b2a = *(const float2*)(xb+o2);
        gE0 = grayv(pix_u8(r2a.x), pix_u8(g2a.x), pix_u8(b2a.x));
        gO0 = grayv(pix_u8(r2a.y), pix_u8(g2a.y), pix_u8(b2a.y));
        float2 r2b = *(const float2*)(xr+o1), g2b = *(const float2*)(xg+o1), b2b = *(const float2*)(xb+o1);
        gE1 = grayv(pix_u8(r2b.x), pix_u8(g2b.x), pix_u8(b2b.x));
        gO1 = grayv(pix_u8(r2b.y), pix_u8(g2b.y), pix_u8(b2b.y));
        if (edge){
            int oa2 = rm2*WW+colA, ob2 = rm2*WW+colB, oa1 = rm1*WW+colA, ob1 = rm1*WW+colB;
            gA0 = grayv(pix_u8(xr[oa2]), pix_u8(xg[oa2]), pix_u8(xb[oa2]));
            gB0 = grayv(pix_u8(xr[ob2]), pix_u8(xg[ob2]), pix_u8(xb[ob2]));
            gA1 = grayv(pix_u8(xr[oa1]), pix_u8(xg[oa1]), pix_u8(xb[oa1]));
            gB1 = grayv(pix_u8(xr[ob1]), pix_u8(xg[ob1]), pix_u8(xb[ob1]));
        }
    }

    // mag histories for rows e-1 (a) and e (b): mid-even, mid-odd, left-of-even, right-of-odd
    float mEa=0,mOa=0,mOla=0,mEra=0;
    float mEb=0,mOb=0,mOlb=0,mErb=0;
    int binEb=0,binOb=0;

    for (int r = r0-1; r <= r0+BAND; ++r){
        // load gray row r+1 (clamped; r+1 >= 0 always)
        int rn = min(r+1, HH-1);
        int off = rn*WW + cE;
        float2 r2 = *(const float2*)(xr+off);
        float2 g2 = *(const float2*)(xg+off);
        float2 b2 = *(const float2*)(xb+off);
        gE2 = grayv(pix_u8(r2.x), pix_u8(g2.x), pix_u8(b2.x));
        gO2 = grayv(pix_u8(r2.y), pix_u8(g2.y), pix_u8(b2.y));
        if (edge){
            int oa = rn*WW+colA, ob = rn*WW+colB;
            gA2 = grayv(pix_u8(xr[oa]), pix_u8(xg[oa]), pix_u8(xb[oa]));
            gB2 = grayv(pix_u8(xr[ob]), pix_u8(xg[ob]), pix_u8(xb[ob]));
        }

        // vertical separable combos for mag row r
        float vsE = gE0 + 2.0f*gE1 + gE2, vdE = gE2 - gE0;
        float vsO = gO0 + 2.0f*gO1 + gO2, vdO = gO2 - gO0;
        float vsA = gA0 + 2.0f*gA1 + gA2, vdA = gA2 - gA0;
        float vsB = gB0 + 2.0f*gB1 + gB2, vdB = gB2 - gB0;

        float vsOl = __shfl_up_sync(0xffffffffu, vsO, 1);   // col 2k-1
        float vdOl = __shfl_up_sync(0xffffffffu, vdO, 1);
        float vsEr = __shfl_down_sync(0xffffffffu, vsE, 1); // col 2k+2
        float vdEr = __shfl_down_sync(0xffffffffu, vdE, 1);
        if (eL){ vsOl = vsA; vdOl = vdA; }
        if (eR){ vsEr = vsA; vdEr = vdA; }

        // Sobel row r: gx(c) = vs(c+1)-vs(c-1); gy(c) = vd(c-1)+2vd(c)+vd(c+1)
        float gxE = vsO - vsOl;
        float gyE = vdOl + 2.0f*vdE + vdO;
        float gxO = vsEr - vsE;
        float gyO = vdE + 2.0f*vdO + vdEr;
        float mE = fabsf(gxE) + fabsf(gyE);
        float mO = fabsf(gxO) + fabsf(gyO);

        // mag at halo col (colA): zero if outside image (zero-pad of mp)
        float magA = 0.0f;
        if (edge && !Aout){
            float gxA = eL ? (vsE - vsB) : (vsB - vsO);
            float gyA = eL ? (vdB + 2.0f*vdA + vdE) : (vdO + 2.0f*vdA + vdB);
            magA = fabsf(gxA) + fabsf(gyA);
        }

        float mOl = __shfl_up_sync(0xffffffffu, mO, 1);
        float mEr = __shfl_down_sync(0xffffffffu, mE, 1);
        if (eL) mOl = magA;
        if (eR) mEr = magA;

        if (r < 0 || r >= HH){ mE=0.0f; mO=0.0f; mOl=0.0f; mEr=0.0f; }

        int binE = binOf(gxE, gyE);
        int binO = binOf(gxO, gyO);

        // emit row e = r-1 (needs mag rows e-1, e, e+1)
        if (r > r0){
            // even col: left=odd col 2k-1 (mOl*), right=odd col 2k (mO*)
            float m  = mEb;
            float q1 = binEb==0 ? mOb  : binEb==1 ? mO  : binEb==2 ? mE  : mOa;
            float q2 = binEb==0 ? mOlb : binEb==1 ? mOla: binEb==2 ? mEa : mOl;
            bool okE = (m >= q1) && (m >= q2);
            bool sE = okE && (m > 85.0f);
            bool wE = okE && (m > 40.0f);
            // odd col: left=even col 2k (mE*), right=even col 2k+2 (mEr*)
            float mo = mOb;
            float p1 = binOb==0 ? mErb : binOb==1 ? mEr : binOb==2 ? mO  : mEra;
            float p2 = binOb==0 ? mEb  : binOb==1 ? mEa : binOb==2 ? mOa : mE;
            bool okO = (mo >= p1) && (mo >= p2);
            bool sO = okO && (mo > 85.0f);
            bool wO = okO && (mo > 40.0f);

            unsigned sEw = __ballot_sync(0xffffffffu, sE);
            unsigned sOw = __ballot_sync(0xffffffffu, sO);
            unsigned wEw = __ballot_sync(0xffffffffu, wE);
            unsigned wOw = __ballot_sync(0xffffffffu, wO);
            if (lane == 0){
                int e = r-1;
                g_strong[b][e][warp] = spread1(sEw) | (spread1(sOw) << 1);
                g_weak  [b][e][warp] = spread1(wEw) | (spread1(wOw) << 1);
            }
        }

        // rotate histories
        mEa=mEb; mOa=mOb; mOla=mOlb; mEra=mErb;
        mEb=mE;  mOb=mO;  mOlb=mOl;  mErb=mEr;
        binEb=binE; binOb=binO;
        gE0=gE1; gE1=gE2; gO0=gO1; gO1=gO2;
        gA0=gA1; gA1=gA2; gB0=gB1; gB1=gB2;
    }
}

// One CTA per image, one thread per row, row state = 8x u64 in registers.
// Double-buffered boundary smem -> ONE barrier per iteration; convergence flag
// tested one iteration late (exact: prev step changed nothing => fixed point).
__global__ __launch_bounds__(512) void canny_hyst(float* __restrict__ out){
    __shared__ unsigned long long hb[2][16][2][8];
    __shared__ unsigned long long sb2[512][8];

    int b    = blockIdx.x;
    int r    = threadIdx.x;
    int lane = r & 31;
    int warp = r >> 5;

    unsigned long long w[8], s[8];
    #pragma unroll
    for (int i = 0; i < 8; i++){ w[i] = g_weak[b][r][i]; s[i] = g_strong[b][r][i]; }

    bool chprev = true;
    for (int it = 0; it < 100; ++it){
        int buf = it & 1;
        unsigned long long h[8];
        #pragma unroll
        for (int i = 0; i < 8; i++) h[i] = s[i] | (s[i] << 1) | (s[i] >> 1);
        #pragma unroll
        for (int i = 0; i < 7; i++){ h[i+1] |= s[i] >> 63; h[i] |= s[i+1] << 63; }

        unsigned long long up[8], dn[8];
        #pragma unroll
        for (int i = 0; i < 8; i++){
            up[i] = __shfl_up_sync  (0xffffffffu, h[i], 1);
            dn[i] = __shfl_down_sync(0xffffffffu, h[i], 1);
        }
        if (lane == 0){
            #pragma unroll
            for (int i = 0; i < 8; i++) hb[buf][warp][0][i] = h[i];
        }
        if (lane == 31){
            #pragma unroll
            for (int i = 0; i < 8; i++) hb[buf][warp][1][i] = h[i];
        }
        // single barrier: orders this iter's hb writes vs reads; convergence
        // is the PREVIOUS iteration's change flag (s already at fixed point).
        if (!__syncthreads_or(chprev)) break;

        if (lane == 0){
            if (warp > 0){
                #pragma unroll
                for (int i = 0; i < 8; i++) up[i] = hb[buf][warp-1][1][i];
            } else {
                #pragma unroll
                for (int i = 0; i < 8; i++) up[i] = 0ull;
            }
        }
        if (lane == 31){
            if (warp < 15){
                #pragma unroll
                for (int i = 0; i < 8; i++) dn[i] = hb[buf][warp+1][0][i];
            } else {
                #pragma unroll
                for (int i = 0; i < 8; i++) dn[i] = 0ull;
            }
        }

        unsigned long long ch = 0ull;
        #pragma unroll
        for (int i = 0; i < 8; i++){
            unsigned long long ns = (h[i] | up[i] | dn[i]) & w[i];
            ch |= ns ^ s[i];
            s[i] = ns;
        }
        chprev = (ch != 0ull);
    }

    #pragma unroll
    for (int i = 0; i < 8; i++) sb2[r][i] = s[i];
    __syncthreads();

    float* o = out + (size_t)b * HW;
    for (int j = threadIdx.x; j < HW/4; j += 512){
        int pix = j << 2;
        unsigned long long wv = sb2[pix >> 9][(pix >> 6) & 7];
        int sh = pix & 63;
        float4 v;
        v.x = ((wv >> (sh    )) & 1ull) ? 255.0f : 0.0f;
        v.y = ((wv >> (sh + 1)) & 1ull) ? 255.0f : 0.0f;
        v.z = ((wv >> (sh + 2)) & 1ull) ? 255.0f : 0.0f;
        v.w = ((wv >> (sh + 3)) & 1ull) ? 255.0f : 0.0f;
        ((float4*)o)[j] = v;
    }
}

extern "C" void kernel_launch(void* const* d_in, const int* in_sizes, int n_in,
                              void* d_out, int out_size){
    const float* x = (const float*)d_in[0];
    dim3 g1(HH/BAND, BI), b1(256, 1, 1);
    canny_stage1<<<g1, b1>>>(x);
    canny_hyst<<<BI, 512>>>((float*)d_out);
}

// round 4
// speedup vs baseline: 1.5387x; 1.5387x over previous
#include <cuda_runtime.h>
#include <cstdint>

#define BI 32
#define HH 512
#define WW 512
#define HW (HH*WW)

// Bitmask scratch: bit c of word i of row r = pixel (r, i*64+c)
__device__ unsigned long long g_strong[BI][HH][8];
__device__ unsigned long long g_weak[BI][HH][8];

// u8 = floor(clip((x+1)*0.5*256, 0, 255)); (v+1)*0.5*256 == (v+1)*128 exactly
__device__ __forceinline__ float pix_u8(float v){
    float t = __fmul_rn(__fadd_rn(v, 1.0f), 128.0f);
    t = fminf(fmaxf(t, 0.0f), 255.0f);
    return floorf(t);
}

// gray = round(0.299r + 0.587g + 0.114b), no FMA contraction, left-assoc, round-half-even
__device__ __forceinline__ float grayv(float r, float g, float b){
    return rintf(__fadd_rn(__fadd_rn(__fmul_rn(0.299f, r), __fmul_rn(0.587f, g)),
                           __fmul_rn(0.114f, b)));
}

// Exact fp32 integer direction binning (gx,gy integers, |.| <= 1020; all products < 2^24)
//   b0: ay < (sqrt2-1)*ax  <=>  (ay+ax)^2 < 2*ax^2
//   b2: ay > (sqrt2+1)*ax  <=>  (ay>ax) && (ay-ax)^2 > 2*ax^2
__device__ __forceinline__ int binOf(float gx, float gy){
    float ax = fabsf(gx), ay = fabsf(gy);
    float sum = __fadd_rn(ax, ay);
    float a2  = __fmul_rn(2.0f, __fmul_rn(ax, ax));
    if (__fmul_rn(sum, sum) < a2) return 0;
    float dif = __fadd_rn(ay, -ax);
    if (dif > 0.0f && __fmul_rn(dif, dif) > a2) return 2;
    return (__fmul_rn(gx, gy) > 0.0f) ? 1 : 3;
}

#define TW 64
#define TH 64
#define GW (TW+4)   // 68
#define GH (TH+4)   // 68
#define MW (TW+2)   // 66
#define MH (TH+2)   // 66

__global__ __launch_bounds__(256) void canny_stage1(const float* __restrict__ x){
    __shared__ float gs[GH][GW];            // gray, replicate-clamped halo 2
    __shared__ float ms[MH][MW];            // |gx|+|gy|, zero outside image, halo 1
    __shared__ unsigned char bs[MH][MW];    // direction bin (valid where in-image)

    int b    = blockIdx.z;
    int col0 = blockIdx.x * TW;
    int row0 = blockIdx.y * TH;
    int tid  = threadIdx.y * 64 + threadIdx.x;

    const float* xr = x + (size_t)b * 3 * HW;
    const float* xg = xr + HW;
    const float* xb = xg + HW;

    // Phase 1: gray tile with halo-2 (replicate border, matching pad mode 'edge')
    for (int idx = tid; idx < GH*GW; idx += 256){
        int j = idx / GW, i = idx % GW;
        int r = row0 - 2 + j; r = min(max(r, 0), HH-1);
        int c = col0 - 2 + i; c = min(max(c, 0), WW-1);
        int off = r*WW + c;
        gs[j][i] = grayv(pix_u8(xr[off]), pix_u8(xg[off]), pix_u8(xb[off]));
    }
    __syncthreads();

    // Phase 2: L1 gradient magnitude + direction bin, halo 1 (zero outside image)
    for (int idx = tid; idx < MH*MW; idx += 256){
        int j = idx / MW, i = idx % MW;
        int r = row0 - 1 + j, c = col0 - 1 + i;
        float m = 0.0f;
        int bin = 0;
        if (r >= 0 && r < HH && c >= 0 && c < WW){
            int jj = j + 1, ii = i + 1;  // into gs
            float g00 = gs[jj-1][ii-1], g01 = gs[jj-1][ii], g02 = gs[jj-1][ii+1];
            float g10 = gs[jj  ][ii-1],                     g12 = gs[jj  ][ii+1];
            float g20 = gs[jj+1][ii-1], g21 = gs[jj+1][ii], g22 = gs[jj+1][ii+1];
            float gx = (g02 + 2.0f*g12 + g22) - (g00 + 2.0f*g10 + g20);
            float gy = (g20 + 2.0f*g21 + g22) - (g00 + 2.0f*g01 + g02);
            m = fabsf(gx) + fabsf(gy);   // exact integer in f32
            bin = binOf(gx, gy);
        }
        ms[j][i] = m;
        bs[j][i] = (unsigned char)bin;
    }
    __syncthreads();

    // Phase 3: NMS + thresholds -> bitmasks (warp lanes = 32 consecutive columns)
    int xt   = threadIdx.x;       // 0..63
    int lane = xt & 31;
    int wsel = xt >> 5;
    const float* msf = &ms[0][0];
    for (int k = 0; k < TH/4; ++k){
        int ty = threadIdx.y + 4*k;   // 0..TH-1
        int cidx = (ty+1)*MW + (xt+1);
        float m  = msf[cidx];
        int bin  = bs[ty+1][xt+1];
        // antisymmetric neighbor offsets: q1 at +o1, q2 at -o1
        // bin0: (0,+1); bin1: (+1,+1); bin2: (+1,0); bin3: (-1,+1)
        int o1 = (bin==0) ? 1 : (bin==1) ? (MW+1) : (bin==2) ? MW : (1-MW);
        float q1 = msf[cidx + o1];
        float q2 = msf[cidx - o1];
        bool ok = (m >= q1) && (m >= q2);

        unsigned sbits = __ballot_sync(0xffffffffu, ok && (m > 85.0f));
        unsigned wbits = __ballot_sync(0xffffffffu, ok && (m > 40.0f));
        if (lane == 0){
            int grow = row0 + ty;
            int word = (col0 >> 5) + wsel;
            ((unsigned*)g_strong)[((size_t)b*HH + grow)*16 + word] = sbits;
            ((unsigned*)g_weak  )[((size_t)b*HH + grow)*16 + word] = wbits;
        }
    }
}

// One CTA per image, one thread per row, row state = 8x u64 in registers.
// s_{k+1} = weak & dilate3x3(s_k); monotone, so early exit on convergence is exact.
__global__ __launch_bounds__(512) void canny_hyst(float* __restrict__ out){
    __shared__ unsigned long long hb[16][2][8];   // per-warp boundary rows (h of lane0 / lane31)
    __shared__ unsigned long long sb2[512][8];    // final bits for coalesced output

    int b    = blockIdx.x;
    int r    = threadIdx.x;
    int lane = r & 31;
    int warp = r >> 5;

    unsigned long long w[8], s[8];
    #pragma unroll
    for (int i = 0; i < 8; i++){ w[i] = g_weak[b][r][i]; s[i] = g_strong[b][r][i]; }

    for (int it = 0; it < 100; ++it){
        unsigned long long h[8];
        #pragma unroll
        for (int i = 0; i < 8; i++) h[i] = s[i] | (s[i] << 1) | (s[i] >> 1);
        #pragma unroll
        for (int i = 0; i < 7; i++){ h[i+1] |= s[i] >> 63; h[i] |= s[i+1] << 63; }

        unsigned long long up[8], dn[8];
        #pragma unroll
        for (int i = 0; i < 8; i++){
            up[i] = __shfl_up_sync  (0xffffffffu, h[i], 1);
            dn[i] = __shfl_down_sync(0xffffffffu, h[i], 1);
        }
        if (lane == 0){
            #pragma unroll
            for (int i = 0; i < 8; i++) hb[warp][0][i] = h[i];
        }
        if (lane == 31){
            #pragma unroll
            for (int i = 0; i < 8; i++) hb[warp][1][i] = h[i];
        }
        __syncthreads();
        if (lane == 0){
            if (warp > 0){
                #pragma unroll
                for (int i = 0; i < 8; i++) up[i] = hb[warp-1][1][i];
            } else {
                #pragma unroll
                for (int i = 0; i < 8; i++) up[i] = 0ull;   // row -1 outside: dilation sees false
            }
        }
        if (lane == 31){
            if (warp < 15){
                #pragma unroll
                for (int i = 0; i < 8; i++) dn[i] = hb[warp+1][0][i];
            } else {
                #pragma unroll
                for (int i = 0; i < 8; i++) dn[i] = 0ull;   // row 512 outside
            }
        }

        unsigned long long ch = 0ull;
        #pragma unroll
        for (int i = 0; i < 8; i++){
            unsigned long long ns = (h[i] | up[i] | dn[i]) & w[i];
            ch |= ns ^ s[i];
            s[i] = ns;
        }
        // barrier also orders this iter's smem reads vs next iter's writes
        if (!__syncthreads_or(ch != 0ull)) break;
    }

    #pragma unroll
    for (int i = 0; i < 8; i++) sb2[r][i] = s[i];
    __syncthreads();

    float* o = out + (size_t)b * HW;
    for (int j = threadIdx.x; j < HW/4; j += 512){
        int pix = j << 2;
        unsigned long long wv = sb2[pix >> 9][(pix >> 6) & 7];
        int sh = pix & 63;
        float4 v;
        v.x = ((wv >> (sh    )) & 1ull) ? 255.0f : 0.0f;
        v.y = ((wv >> (sh + 1)) & 1ull) ? 255.0f : 0.0f;
        v.z = ((wv >> (sh + 2)) & 1ull) ? 255.0f : 0.0f;
        v.w = ((wv >> (sh + 3)) & 1ull) ? 255.0f : 0.0f;
        ((float4*)o)[j] = v;
    }
}

extern "C" void kernel_launch(void* const* d_in, const int* in_sizes, int n_in,
                              void* d_out, int out_size){
    const float* x = (const float*)d_in[0];
    dim3 g1(WW/TW, HH/TH, BI), b1(64, 4, 1);
    canny_stage1<<<g1, b1>>>(x);
    canny_hyst<<<BI, 512>>>((float*)d_out);
}